// round 7
// baseline (speedup 1.0000x reference)
#include <cuda_runtime.h>
#include <cuda_bf16.h>
#include <math_constants.h>
#include <cstdint>

// Problem dims
#define BB   2
#define SS   2048
#define HID  2048
#define NH   16
#define NKV  4
#define HD   128
#define RR   64
#define NTOK (BB*SS)          // 4096
#define QKVO ((NH+2*NKV)*HD)  // 3072

// Scratch (device globals; no allocation allowed)
__device__ float g_qkv[(size_t)NTOK * QKVO];                    // fp32 QKV out
__device__ __nv_bfloat16 g_xh[(size_t)NTOK * HID];              // hidden / attn hi
__device__ __nv_bfloat16 g_xl[(size_t)NTOK * HID];              // hidden / attn lo
__device__ __nv_bfloat16 g_wh[(size_t)QKVO * HID];              // weight hi
__device__ __nv_bfloat16 g_wl[(size_t)QKVO * HID];              // weight lo
__device__ __nv_bfloat16 g_qh[(size_t)BB * NH  * SS * HD];
__device__ __nv_bfloat16 g_ql[(size_t)BB * NH  * SS * HD];
__device__ __nv_bfloat16 g_kh[(size_t)BB * NKV * SS * HD];
__device__ __nv_bfloat16 g_kl[(size_t)BB * NKV * SS * HD];
__device__ __nv_bfloat16 g_vh[(size_t)BB * NKV * SS * HD];
__device__ __nv_bfloat16 g_vl[(size_t)BB * NKV * SS * HD];

// ---------------------------------------------------------------------------
// PTX helpers (base PTX only — compute_103-safe)
// ---------------------------------------------------------------------------
__device__ __forceinline__ void mma_bf16(float* c, const uint32_t* a, const uint32_t* b) {
    asm volatile(
        "mma.sync.aligned.m16n8k16.row.col.f32.bf16.bf16.f32 "
        "{%0,%1,%2,%3}, {%4,%5,%6,%7}, {%8,%9}, {%0,%1,%2,%3};"
        : "+f"(c[0]), "+f"(c[1]), "+f"(c[2]), "+f"(c[3])
        : "r"(a[0]), "r"(a[1]), "r"(a[2]), "r"(a[3]), "r"(b[0]), "r"(b[1]));
}

__device__ __forceinline__ void ldsm_x4(uint32_t* r, uint32_t addr) {
    asm volatile("ldmatrix.sync.aligned.m8n8.x4.shared.b16 {%0,%1,%2,%3}, [%4];"
        : "=r"(r[0]), "=r"(r[1]), "=r"(r[2]), "=r"(r[3]) : "r"(addr));
}

__device__ __forceinline__ void ldsm_x4_t(uint32_t* r, uint32_t addr) {
    asm volatile("ldmatrix.sync.aligned.m8n8.x4.trans.shared.b16 {%0,%1,%2,%3}, [%4];"
        : "=r"(r[0]), "=r"(r[1]), "=r"(r[2]), "=r"(r[3]) : "r"(addr));
}

__device__ __forceinline__ uint32_t smem_u32(const void* p) {
    uint32_t a;
    asm("{ .reg .u64 t; cvta.to.shared.u64 t, %1; cvt.u32.u64 %0, t; }"
        : "=r"(a) : "l"(p));
    return a;
}

#define CP_ASYNC16(saddr, gptr) \
    asm volatile("cp.async.cg.shared.global [%0], [%1], 16;" \
                 :: "r"(saddr), "l"(gptr))
#define CP_COMMIT() asm volatile("cp.async.commit_group;" ::: "memory")
#define CP_WAIT(n)  asm volatile("cp.async.wait_group %0;" :: "n"(n) : "memory")

__device__ __forceinline__ uint32_t bf16hi2(float x, float y) {
    __nv_bfloat162 h = __floats2bfloat162_rn(x, y);
    return *(uint32_t*)&h;
}

__device__ __forceinline__ void split4(float4 v, uint2& hi, uint2& lo) {
    uint32_t h0 = bf16hi2(v.x, v.y);
    uint32_t h1 = bf16hi2(v.z, v.w);
    __nv_bfloat162 hh0 = *(__nv_bfloat162*)&h0;
    __nv_bfloat162 hh1 = *(__nv_bfloat162*)&h1;
    uint32_t l0 = bf16hi2(v.x - __bfloat162float(hh0.x), v.y - __bfloat162float(hh0.y));
    uint32_t l1 = bf16hi2(v.z - __bfloat162float(hh1.x), v.w - __bfloat162float(hh1.y));
    hi = make_uint2(h0, h1);
    lo = make_uint2(l0, l1);
}

// ---------------------------------------------------------------------------
// Elementwise fp32 -> bf16 hi/lo split
// ---------------------------------------------------------------------------
__global__ __launch_bounds__(256) void split_kernel(
    const float* __restrict__ in, __nv_bfloat16* __restrict__ hi,
    __nv_bfloat16* __restrict__ lo, int n4)
{
    int i = blockIdx.x * blockDim.x + threadIdx.x;
    if (i < n4) {
        float4 v = ((const float4*)in)[i];
        uint2 h, l;
        split4(v, h, l);
        ((uint2*)hi)[i] = h;
        ((uint2*)lo)[i] = l;
    }
}

// ---------------------------------------------------------------------------
// Tensor GEMM: C[M,N] = A[M,K] * B[N,K]^T with pre-split bf16 hi/lo inputs.
// 128x128 tile, BK=32, 256 threads, cp.async double-buffer, ldmatrix.
// ---------------------------------------------------------------------------
#define TBK 32
#define ASTR 40
#define ARR (128 * ASTR)
#define STAGE_BF16 (4 * ARR)
#define GEMM_SMEM (2 * STAGE_BF16 * 2)

__global__ __launch_bounds__(256, 1) void gemm_mma_kernel(
    const __nv_bfloat16* __restrict__ Ah, const __nv_bfloat16* __restrict__ Al,
    const __nv_bfloat16* __restrict__ Bh, const __nv_bfloat16* __restrict__ Bl,
    float* __restrict__ C, int N, int K)
{
    extern __shared__ __nv_bfloat16 smb[];
    const int tid  = threadIdx.x;
    const int wid  = tid >> 5;
    const int lane = tid & 31;
    const int wm   = wid >> 2;
    const int wn   = wid & 3;
    const int row0 = blockIdx.y * 128;
    const int col0 = blockIdx.x * 128;

    const int lr = lane >> 2;
    const int lc = (lane & 3) * 2;

    const uint32_t sb = smem_u32(smb);
    const uint32_t laneA = ((lane & 15) * ASTR + (lane >> 4) * 8) * 2;
    const uint32_t laneB = (((lane >> 4) * 8 + (lane & 7)) * ASTR + ((lane >> 3) & 1) * 8) * 2;

    float acc[4][4][4];
    #pragma unroll
    for (int mt = 0; mt < 4; ++mt)
        #pragma unroll
        for (int nt = 0; nt < 4; ++nt)
            #pragma unroll
            for (int q = 0; q < 4; ++q) acc[mt][nt][q] = 0.f;

    const int nchunk = K / TBK;

    const __nv_bfloat16* srcs[4] = {
        Ah + (size_t)row0 * K, Al + (size_t)row0 * K,
        Bh + (size_t)col0 * K, Bl + (size_t)col0 * K };

    auto issue_chunk = [&](int ic, int stg) {
        uint32_t sbase = sb + (uint32_t)stg * (STAGE_BF16 * 2);
        #pragma unroll
        for (int arr = 0; arr < 4; ++arr) {
            #pragma unroll
            for (int it = 0; it < 2; ++it) {
                int id = tid + it * 256;
                int r = id >> 2, g = id & 3;
                CP_ASYNC16(sbase + (uint32_t)arr * (ARR * 2)
                               + (uint32_t)(r * ASTR * 2 + g * 16),
                           srcs[arr] + (size_t)r * K + (size_t)ic * TBK + g * 8);
            }
        }
    };

    issue_chunk(0, 0);
    CP_COMMIT();

    for (int ic = 0; ic < nchunk; ++ic) {
        const int cur = ic & 1;
        if (ic + 1 < nchunk) {
            issue_chunk(ic + 1, 1 - cur);
            CP_COMMIT();
            CP_WAIT(1);
        } else {
            CP_WAIT(0);
        }
        __syncthreads();

        const uint32_t stOff = (uint32_t)cur * (STAGE_BF16 * 2);
        const uint32_t aBase = sb + stOff + (uint32_t)(wm * 64) * (ASTR * 2) + laneA;
        const uint32_t bBase = sb + stOff + (uint32_t)(2 * ARR) * 2
                             + (uint32_t)(wn * 32) * (ASTR * 2) + laneB;

        #pragma unroll
        for (int ks = 0; ks < 2; ++ks) {
            const uint32_t kkB = ks * 32;
            uint32_t ah[4][4], al[4][4], bh[2][4], bl[2][4];
            #pragma unroll
            for (int mt = 0; mt < 4; ++mt) {
                ldsm_x4(ah[mt], aBase + (uint32_t)mt * (16 * ASTR * 2) + kkB);
                ldsm_x4(al[mt], aBase + (uint32_t)(ARR * 2) + (uint32_t)mt * (16 * ASTR * 2) + kkB);
            }
            #pragma unroll
            for (int np = 0; np < 2; ++np) {
                ldsm_x4(bh[np], bBase + (uint32_t)np * (16 * ASTR * 2) + kkB);
                ldsm_x4(bl[np], bBase + (uint32_t)(ARR * 2) + (uint32_t)np * (16 * ASTR * 2) + kkB);
            }
            #pragma unroll
            for (int mt = 0; mt < 4; ++mt)
                #pragma unroll
                for (int nt = 0; nt < 4; ++nt) {
                    const uint32_t* pbh = &bh[nt >> 1][(nt & 1) * 2];
                    const uint32_t* pbl = &bl[nt >> 1][(nt & 1) * 2];
                    mma_bf16(acc[mt][nt], ah[mt], pbh);
                    mma_bf16(acc[mt][nt], ah[mt], pbl);
                    mma_bf16(acc[mt][nt], al[mt], pbh);
                }
        }
        __syncthreads();
    }

    #pragma unroll
    for (int mt = 0; mt < 4; ++mt) {
        int row = row0 + wm * 64 + mt * 16 + lr;
        #pragma unroll
        for (int nt = 0; nt < 4; ++nt) {
            int col = col0 + wn * 32 + nt * 8 + lc;
            *(float2*)&C[(size_t)row * N + col] =
                make_float2(acc[mt][nt][0], acc[mt][nt][1]);
            *(float2*)&C[(size_t)(row + 8) * N + col] =
                make_float2(acc[mt][nt][2], acc[mt][nt][3]);
        }
    }
}

// ---------------------------------------------------------------------------
// Per-head RMSNorm + RoPE + split into bf16 hi/lo Q/K/V tensors.
// ---------------------------------------------------------------------------
__global__ __launch_bounds__(128) void prep_kernel(
    const float* __restrict__ cos_t, const float* __restrict__ sin_t,
    const float* __restrict__ q_ln, const float* __restrict__ k_ln)
{
    const int hh = blockIdx.x;
    const int s  = blockIdx.y;
    const int b  = blockIdx.z;
    const int d  = threadIdx.x;

    const size_t t = (size_t)b * SS + s;
    float x = g_qkv[t * QKVO + hh * HD + d];

    __shared__ float sy[HD];
    __shared__ float red[4];

    const float qscale = 0.08838834764831845f;  // 1/sqrt(128)

    if (hh < NH + NKV) {
        float sq = x * x;
        #pragma unroll
        for (int o = 16; o; o >>= 1) sq += __shfl_xor_sync(0xFFFFFFFFu, sq, o);
        if ((d & 31) == 0) red[d >> 5] = sq;
        __syncthreads();
        float var = (red[0] + red[1] + red[2] + red[3]) * (1.f / HD);
        const float* w = (hh < NH) ? q_ln : k_ln;
        float y = x * rsqrtf(var + 1e-6f) * w[d];
        sy[d] = y;
        __syncthreads();

        float out = y;
        if (d < RR) {
            float c  = cos_t[t * RR + d];
            float sn = sin_t[t * RR + d];
            float rot = (d < RR / 2) ? -sy[d + RR / 2] : sy[d - RR / 2];
            out = fmaf(y, c, rot * sn);
        }
        if (hh < NH) {
            out *= qscale;
            size_t off = (((size_t)(b * NH + hh)) * SS + s) * HD + d;
            __nv_bfloat16 hi = __float2bfloat16(out);
            g_qh[off] = hi;
            g_ql[off] = __float2bfloat16(out - __bfloat162float(hi));
        } else {
            size_t off = (((size_t)(b * NKV + (hh - NH))) * SS + s) * HD + d;
            __nv_bfloat16 hi = __float2bfloat16(out);
            g_kh[off] = hi;
            g_kl[off] = __float2bfloat16(out - __bfloat162float(hi));
        }
    } else {
        size_t off = (((size_t)(b * NKV + (hh - NH - NKV))) * SS + s) * HD + d;
        __nv_bfloat16 hi = __float2bfloat16(x);
        g_vh[off] = hi;
        g_vl[off] = __float2bfloat16(x - __bfloat162float(hi));
    }
}

// ---------------------------------------------------------------------------
// Flash attention on mma.sync, pre-split bf16 inputs, cp.async double-buffered
// K/V, ldmatrix fragments. CTA: 128 q x (b,h), 8 warps (16 q-rows each).
// Output written directly as split bf16 into g_xh/g_xl.
// ---------------------------------------------------------------------------
#define DSTR 136
#define KVSTAGE (4 * 64 * DSTR)            // bf16 per stage (Khi,Klo,Vhi,Vlo)
#define AQ_BF16 (2 * 128 * DSTR)           // Qhi + Qlo
#define ATTN2_SMEM ((AQ_BF16 + 2 * KVSTAGE) * 2)   // ~204 KB

__global__ __launch_bounds__(256, 1) void attn_mma_kernel()
{
    extern __shared__ __nv_bfloat16 smb[];
    __nv_bfloat16* Qhi = smb;
    __nv_bfloat16* Qlo = Qhi + 128 * DSTR;

    const int tid  = threadIdx.x;
    const int wid  = tid >> 5;
    const int lane = tid & 31;
    const int gr   = lane >> 2;
    const int gc   = (lane & 3) * 2;
    const int q0 = blockIdx.x * 128;
    const int bh = blockIdx.y;
    const int b = bh >> 4;
    const int h = bh & 15;
    const int hk = h / (NH / NKV);
    const int m0 = wid * 16;

    const uint32_t sb = smem_u32(smb);
    const uint32_t kvOff = sb + (uint32_t)AQ_BF16 * 2;
    const uint32_t laneA = ((lane & 15) * DSTR + (lane >> 4) * 8) * 2;
    const uint32_t laneB = (((lane >> 4) * 8 + (lane & 7)) * DSTR + ((lane >> 3) & 1) * 8) * 2;
    const uint32_t laneV = ((lane & 15) * DSTR + (lane >> 4) * 8) * 2;

    const uint32_t qBaseHi = sb + (uint32_t)(m0 * DSTR) * 2 + laneA;
    const uint32_t qBaseLo = qBaseHi + (uint32_t)(128 * DSTR) * 2;

    const size_t kvg = ((size_t)(b * NKV + hk)) * SS * HD;
    const __nv_bfloat16* srcs[4] = { g_kh + kvg, g_kl + kvg, g_vh + kvg, g_vl + kvg };

    auto issue_kv = [&](int kt, int stg) {
        uint32_t sbase = kvOff + (uint32_t)stg * (KVSTAGE * 2);
        size_t goff = (size_t)kt * 64 * HD;
        #pragma unroll
        for (int arr = 0; arr < 4; ++arr) {
            #pragma unroll
            for (int it = 0; it < 4; ++it) {
                int id = tid + it * 256;
                int r = id >> 4, g = id & 15;
                CP_ASYNC16(sbase + (uint32_t)arr * (64 * DSTR * 2)
                               + (uint32_t)(r * DSTR * 2 + g * 16),
                           srcs[arr] + goff + (size_t)r * HD + g * 8);
            }
        }
    };

    // ---- load Q tile (already scaled + split) ----
    {
        const __nv_bfloat16* qh = &g_qh[(((size_t)(b * NH + h)) * SS + q0) * HD];
        const __nv_bfloat16* ql = &g_ql[(((size_t)(b * NH + h)) * SS + q0) * HD];
        #pragma unroll
        for (int it = 0; it < 8; ++it) {
            int id = tid + it * 256;
            int r = id >> 4, g = id & 15;
            *(uint4*)&Qhi[r * DSTR + g * 8] = *(const uint4*)&qh[(size_t)r * HD + g * 8];
            *(uint4*)&Qlo[r * DSTR + g * 8] = *(const uint4*)&ql[(size_t)r * HD + g * 8];
        }
    }

    issue_kv(0, 0);
    CP_COMMIT();

    float m_[2] = {-CUDART_INF_F, -CUDART_INF_F};
    float l_[2] = {0.f, 0.f};
    float O[16][4];
    #pragma unroll
    for (int nt = 0; nt < 16; ++nt)
        #pragma unroll
        for (int q = 0; q < 4; ++q) O[nt][q] = 0.f;

    for (int kt = 0; kt < SS / 64; ++kt) {
        const int cur = kt & 1;
        if (kt + 1 < SS / 64) {
            issue_kv(kt + 1, 1 - cur);
            CP_COMMIT();
            CP_WAIT(1);
        } else {
            CP_WAIT(0);
        }
        __syncthreads();

        const uint32_t st = kvOff + (uint32_t)cur * (KVSTAGE * 2);
        const uint32_t kBaseHi = st + laneB;
        const uint32_t kBaseLo = kBaseHi + (uint32_t)(64 * DSTR) * 2;
        const uint32_t vBaseHi = st + (uint32_t)(2 * 64 * DSTR) * 2 + laneV;
        const uint32_t vBaseLo = vBaseHi + (uint32_t)(64 * DSTR) * 2;

        // ---- S = Q K^T ----
        float sc[8][4];
        #pragma unroll
        for (int nt = 0; nt < 8; ++nt)
            #pragma unroll
            for (int q = 0; q < 4; ++q) sc[nt][q] = 0.f;

        #pragma unroll
        for (int ks = 0; ks < 8; ++ks) {
            const uint32_t kkB = ks * 32;
            uint32_t qh[4], ql[4];
            ldsm_x4(qh, qBaseHi + kkB);
            ldsm_x4(ql, qBaseLo + kkB);
            #pragma unroll
            for (int np = 0; np < 4; ++np) {
                uint32_t kb4[4], kl4[4];
                ldsm_x4(kb4, kBaseHi + (uint32_t)np * (16 * DSTR * 2) + kkB);
                ldsm_x4(kl4, kBaseLo + (uint32_t)np * (16 * DSTR * 2) + kkB);
                mma_bf16(sc[2*np],   qh, &kb4[0]);
                mma_bf16(sc[2*np],   qh, &kl4[0]);
                mma_bf16(sc[2*np],   ql, &kb4[0]);
                mma_bf16(sc[2*np+1], qh, &kb4[2]);
                mma_bf16(sc[2*np+1], qh, &kl4[2]);
                mma_bf16(sc[2*np+1], ql, &kb4[2]);
            }
        }

        // ---- online softmax (warp-local) ----
        float mx0 = -CUDART_INF_F, mx1 = -CUDART_INF_F;
        #pragma unroll
        for (int nt = 0; nt < 8; ++nt) {
            mx0 = fmaxf(mx0, fmaxf(sc[nt][0], sc[nt][1]));
            mx1 = fmaxf(mx1, fmaxf(sc[nt][2], sc[nt][3]));
        }
        mx0 = fmaxf(mx0, __shfl_xor_sync(0xFFFFFFFFu, mx0, 1));
        mx0 = fmaxf(mx0, __shfl_xor_sync(0xFFFFFFFFu, mx0, 2));
        mx1 = fmaxf(mx1, __shfl_xor_sync(0xFFFFFFFFu, mx1, 1));
        mx1 = fmaxf(mx1, __shfl_xor_sync(0xFFFFFFFFu, mx1, 2));

        float mn0 = fmaxf(m_[0], mx0);
        float mn1 = fmaxf(m_[1], mx1);
        float scl0 = __expf(m_[0] - mn0);
        float scl1 = __expf(m_[1] - mn1);
        m_[0] = mn0; m_[1] = mn1;

        uint32_t pah[4][4], pal[4][4];
        float rs0 = 0.f, rs1 = 0.f;
        #pragma unroll
        for (int k2 = 0; k2 < 4; ++k2) {
            float p00 = __expf(sc[2*k2][0] - mn0);
            float p01 = __expf(sc[2*k2][1] - mn0);
            float p02 = __expf(sc[2*k2][2] - mn1);
            float p03 = __expf(sc[2*k2][3] - mn1);
            float p10 = __expf(sc[2*k2+1][0] - mn0);
            float p11 = __expf(sc[2*k2+1][1] - mn0);
            float p12 = __expf(sc[2*k2+1][2] - mn1);
            float p13 = __expf(sc[2*k2+1][3] - mn1);
            rs0 += p00 + p01 + p10 + p11;
            rs1 += p02 + p03 + p12 + p13;
            uint32_t hh;
            hh = bf16hi2(p00, p01); pah[k2][0] = hh;
            {   __nv_bfloat162 t = *(__nv_bfloat162*)&hh;
                pal[k2][0] = bf16hi2(p00 - __bfloat162float(t.x), p01 - __bfloat162float(t.y)); }
            hh = bf16hi2(p02, p03); pah[k2][1] = hh;
            {   __nv_bfloat162 t = *(__nv_bfloat162*)&hh;
                pal[k2][1] = bf16hi2(p02 - __bfloat162float(t.x), p03 - __bfloat162float(t.y)); }
            hh = bf16hi2(p10, p11); pah[k2][2] = hh;
            {   __nv_bfloat162 t = *(__nv_bfloat162*)&hh;
                pal[k2][2] = bf16hi2(p10 - __bfloat162float(t.x), p11 - __bfloat162float(t.y)); }
            hh = bf16hi2(p12, p13); pah[k2][3] = hh;
            {   __nv_bfloat162 t = *(__nv_bfloat162*)&hh;
                pal[k2][3] = bf16hi2(p12 - __bfloat162float(t.x), p13 - __bfloat162float(t.y)); }
        }
        rs0 += __shfl_xor_sync(0xFFFFFFFFu, rs0, 1);
        rs0 += __shfl_xor_sync(0xFFFFFFFFu, rs0, 2);
        rs1 += __shfl_xor_sync(0xFFFFFFFFu, rs1, 1);
        rs1 += __shfl_xor_sync(0xFFFFFFFFu, rs1, 2);
        l_[0] = l_[0] * scl0 + rs0;
        l_[1] = l_[1] * scl1 + rs1;

        #pragma unroll
        for (int nt = 0; nt < 16; ++nt) {
            O[nt][0] *= scl0; O[nt][1] *= scl0;
            O[nt][2] *= scl1; O[nt][3] *= scl1;
        }

        // ---- PV ----
        #pragma unroll
        for (int k2 = 0; k2 < 4; ++k2) {
            const uint32_t kOff = (uint32_t)k2 * (16 * DSTR * 2);
            #pragma unroll
            for (int np = 0; np < 8; ++np) {
                uint32_t vb4[4], vl4[4];
                ldsm_x4_t(vb4, vBaseHi + kOff + (uint32_t)np * 32);
                ldsm_x4_t(vl4, vBaseLo + kOff + (uint32_t)np * 32);
                mma_bf16(O[2*np],   pah[k2], &vb4[0]);
                mma_bf16(O[2*np],   pah[k2], &vl4[0]);
                mma_bf16(O[2*np],   pal[k2], &vb4[0]);
                mma_bf16(O[2*np+1], pah[k2], &vb4[2]);
                mma_bf16(O[2*np+1], pah[k2], &vl4[2]);
                mma_bf16(O[2*np+1], pal[k2], &vb4[2]);
            }
        }
        __syncthreads();
    }

    // ---- epilogue: normalize, split, write bf16 hi/lo to g_xh/g_xl ----
    const float inv0 = 1.f / l_[0];
    const float inv1 = 1.f / l_[1];
    const int s0 = q0 + m0 + gr;
    #pragma unroll
    for (int nt = 0; nt < 16; ++nt) {
        int col = nt * 8 + gc;
        size_t off0 = (((size_t)b * SS + s0) * NH + h) * HD + col;
        size_t off1 = (((size_t)b * SS + s0 + 8) * NH + h) * HD + col;
        float a0 = O[nt][0] * inv0, a1 = O[nt][1] * inv0;
        float a2 = O[nt][2] * inv1, a3 = O[nt][3] * inv1;
        uint32_t h0 = bf16hi2(a0, a1);
        __nv_bfloat162 t0 = *(__nv_bfloat162*)&h0;
        uint32_t l0 = bf16hi2(a0 - __bfloat162float(t0.x), a1 - __bfloat162float(t0.y));
        uint32_t h1 = bf16hi2(a2, a3);
        __nv_bfloat162 t1 = *(__nv_bfloat162*)&h1;
        uint32_t l1 = bf16hi2(a2 - __bfloat162float(t1.x), a3 - __bfloat162float(t1.y));
        *(uint32_t*)&g_xh[off0] = h0;
        *(uint32_t*)&g_xl[off0] = l0;
        *(uint32_t*)&g_xh[off1] = h1;
        *(uint32_t*)&g_xl[off1] = l1;
    }
}

// ---------------------------------------------------------------------------
extern "C" void kernel_launch(void* const* d_in, const int* in_sizes, int n_in,
                              void* d_out, int out_size)
{
    const float* hidden  = (const float*)d_in[0];
    const float* cos_t   = (const float*)d_in[1];
    const float* sin_t   = (const float*)d_in[2];
    const float* w_qkv   = (const float*)d_in[3];
    const float* q_ln    = (const float*)d_in[4];
    const float* k_ln    = (const float*)d_in[5];
    const float* w_dense = (const float*)d_in[6];
    float* out = (float*)d_out;

    void *p_qkv, *p_xh, *p_xl, *p_wh, *p_wl;
    cudaGetSymbolAddress(&p_qkv, g_qkv);
    cudaGetSymbolAddress(&p_xh, g_xh);
    cudaGetSymbolAddress(&p_xl, g_xl);
    cudaGetSymbolAddress(&p_wh, g_wh);
    cudaGetSymbolAddress(&p_wl, g_wl);
    float* qkv = (float*)p_qkv;
    __nv_bfloat16* xh = (__nv_bfloat16*)p_xh;
    __nv_bfloat16* xl = (__nv_bfloat16*)p_xl;
    __nv_bfloat16* wh = (__nv_bfloat16*)p_wh;
    __nv_bfloat16* wl = (__nv_bfloat16*)p_wl;

    cudaFuncSetAttribute(gemm_mma_kernel,
                         cudaFuncAttributeMaxDynamicSharedMemorySize, GEMM_SMEM);
    cudaFuncSetAttribute(attn_mma_kernel,
                         cudaFuncAttributeMaxDynamicSharedMemorySize, ATTN2_SMEM);

    // 0) pre-split hidden and w_qkv
    split_kernel<<<(NTOK * HID / 4 + 255) / 256, 256>>>(hidden, xh, xl, NTOK * HID / 4);
    split_kernel<<<(QKVO * HID / 4 + 255) / 256, 256>>>(w_qkv, wh, wl, QKVO * HID / 4);

    // 1) QKV projection
    gemm_mma_kernel<<<dim3(QKVO / 128, NTOK / 128), 256, GEMM_SMEM>>>(
        xh, xl, wh, wl, qkv, QKVO, HID);

    // 2) RMSNorm + RoPE + split into bf16 Q/K/V
    prep_kernel<<<dim3(NH + 2 * NKV, SS, BB), 128>>>(cos_t, sin_t, q_ln, k_ln);

    // 3) Flash attention -> writes split attn output into g_xh/g_xl
    attn_mma_kernel<<<dim3(SS / 128, BB * NH), 256, ATTN2_SMEM>>>();

    // 3b) pre-split w_dense (overwrites g_wh/g_wl, safe after GEMM1)
    split_kernel<<<(HID * HID / 4 + 255) / 256, 256>>>(w_dense, wh, wl, HID * HID / 4);

    // 4) Output projection
    gemm_mma_kernel<<<dim3(HID / 128, NTOK / 128), 256, GEMM_SMEM>>>(
        xh, xl, wh, wl, out, HID, HID);
}